// round 2
// baseline (speedup 1.0000x reference)
#include <cuda_runtime.h>

#define BATCH 4
#define NSEQ  512
#define N_TOK (BATCH * NSEQ)   // 2048
#define D     64
#define TI    32
#define TJ    32

// Scratch for per-token vectors (allocation-free rule: __device__ globals)
__device__ float g_a[N_TOK * D];   // a = emb @ W1[:64] + b1   (b1 folded)
__device__ float g_b[N_TOK * D];   // b = emb @ W1[64:]

// ---------------------------------------------------------------------------
// Phase 1: per-token chain  x -> pos -> proj -> emb -> (a, b)
// 4 tokens per 256-thread block; thread d in [0,64) owns channel d.
// ---------------------------------------------------------------------------
__global__ void precompute_kernel(
    const float* __restrict__ x,
    const float* __restrict__ Wf,  const float* __restrict__ bf,
    const float* __restrict__ Wp1, const float* __restrict__ bp1,
    const float* __restrict__ Wp2, const float* __restrict__ bp2,
    const float* __restrict__ Wn,  const float* __restrict__ bn,
    const float* __restrict__ W1,  const float* __restrict__ b1)
{
    __shared__ float s_x [4][16];
    __shared__ float s_h [4][D];
    __shared__ float s_h2[4][D];

    const int tl = threadIdx.x >> 6;   // token slot 0..3
    const int d  = threadIdx.x & 63;   // channel
    const int t  = blockIdx.x * 4 + tl;

    if (d < 16) s_x[tl][d] = x[t * 16 + d];
    __syncthreads();

    // pos hidden: relu(xyz @ Wp1 + bp1), xyz = x[..., 13:16]
    float ph = bp1[d];
    #pragma unroll
    for (int r = 0; r < 3; r++) ph += s_x[tl][13 + r] * Wp1[r * D + d];
    s_h[tl][d] = fmaxf(ph, 0.f);
    __syncthreads();

    // pos = ph @ Wp2 + bp2 ; proj = feats @ Wf + bf + pos
    float pos = bp2[d];
    #pragma unroll
    for (int k = 0; k < D; k++) pos += s_h[tl][k] * Wp2[k * D + d];
    float proj = bf[d] + pos;
    #pragma unroll
    for (int r = 0; r < 13; r++) proj += s_x[tl][r] * Wf[r * D + d];
    s_h2[tl][d] = proj;
    __syncthreads();

    // emb = proj @ Wn + bn
    float emb = bn[d];
    #pragma unroll
    for (int k = 0; k < D; k++) emb += s_h2[tl][k] * Wn[k * D + d];
    s_h[tl][d] = emb;
    __syncthreads();

    // a = emb @ W1[:64] + b1 ; b = emb @ W1[64:]
    float av = b1[d];
    float bv = 0.f;
    #pragma unroll
    for (int k = 0; k < D; k++) {
        float e = s_h[tl][k];
        av += e * W1[k * D + d];
        bv += e * W1[(D + k) * D + d];
    }
    g_a[t * D + d] = av;
    g_b[t * D + d] = bv;
}

// ---------------------------------------------------------------------------
// Phase 2: pairwise kernel.  One thread per (i,j) pair, 32x32 tile per CTA.
// Inner loop uses packed fma.rn.f32x2 (FFMA2) -> 2x fp32 FMA throughput.
// ---------------------------------------------------------------------------
__global__ void __launch_bounds__(1024, 1)
pair_kernel(const float* __restrict__ W2, const float* __restrict__ b2,
            const float* __restrict__ W3, const float* __restrict__ b3,
            float* __restrict__ out)
{
    __shared__ float a_s [TI * D];          // a rows, row-major [i][k]
    __shared__ float b_sT[D * TJ];          // b transposed     [k][j]
    __shared__ __align__(16) float w2_s[D * 32];  // [k][n]
    __shared__ float b2_s[32];
    __shared__ float w3_s[32];

    const int j   = threadIdx.x;            // 0..31  (lane -> coalesced out)
    const int i   = threadIdx.y;            // 0..31
    const int lin = i * 32 + j;             // 0..1023
    const int batch = blockIdx.z;
    const int i0 = blockIdx.y * TI;
    const int j0 = blockIdx.x * TJ;
    const int base = batch * NSEQ;

    // cooperative loads (2 elems/thread each)
    a_s[lin]        = g_a[(base + i0) * D + lin];
    a_s[lin + 1024] = g_a[(base + i0) * D + lin + 1024];
    {
        int jj = lin >> 6, k = lin & 63;
        b_sT[k * TJ + jj] = g_b[(base + j0 + jj) * D + k];
        int l2 = lin + 1024;
        jj = l2 >> 6; k = l2 & 63;
        b_sT[k * TJ + jj] = g_b[(base + j0 + jj) * D + k];
    }
    w2_s[lin]        = W2[lin];
    w2_s[lin + 1024] = W2[lin + 1024];
    if (lin < 32) { b2_s[lin] = b2[lin]; w3_s[lin] = W3[lin]; }
    __syncthreads();

    // 32 fp32 accumulators packed as 16 x f32x2
    unsigned long long acc[16];
    #pragma unroll
    for (int n = 0; n < 16; n++) acc[n] = 0ull;

    const unsigned long long* w2v = (const unsigned long long*)w2_s;  // [k][16]
    const float* arow = &a_s[i * D];
    const float* bcol = &b_sT[j];

    #pragma unroll 8
    for (int k = 0; k < D; k++) {
        float h = fmaxf(arow[k] + bcol[k * TJ], 0.f);
        unsigned long long h2;
        asm("mov.b64 %0, {%1, %1};" : "=l"(h2) : "r"(__float_as_uint(h)));
        #pragma unroll
        for (int n = 0; n < 16; n++) {
            asm("fma.rn.f32x2 %0, %1, %2, %0;"
                : "+l"(acc[n]) : "l"(h2), "l"(w2v[k * 16 + n]));
        }
    }

    // epilogue: h2 = relu(acc + b2) ; logit = h2 @ W3 + b3
    float logit = b3[0];
    #pragma unroll
    for (int n = 0; n < 16; n++) {
        unsigned int lo, hi;
        asm("mov.b64 {%0, %1}, %2;" : "=r"(lo), "=r"(hi) : "l"(acc[n]));
        float h0 = fmaxf(__uint_as_float(lo) + b2_s[2 * n],     0.f);
        float h1 = fmaxf(__uint_as_float(hi) + b2_s[2 * n + 1], 0.f);
        logit += h0 * w3_s[2 * n] + h1 * w3_s[2 * n + 1];
    }
    out[batch * NSEQ * NSEQ + (i0 + i) * NSEQ + (j0 + j)] = logit;
}

// ---------------------------------------------------------------------------
extern "C" void kernel_launch(void* const* d_in, const int* in_sizes, int n_in,
                              void* d_out, int out_size)
{
    const float* x   = (const float*)d_in[0];
    const float* Wf  = (const float*)d_in[1];
    const float* bf  = (const float*)d_in[2];
    const float* Wp1 = (const float*)d_in[3];
    const float* bp1 = (const float*)d_in[4];
    const float* Wp2 = (const float*)d_in[5];
    const float* bp2 = (const float*)d_in[6];
    const float* Wn  = (const float*)d_in[7];
    const float* bn  = (const float*)d_in[8];
    const float* W1  = (const float*)d_in[9];
    const float* b1  = (const float*)d_in[10];
    const float* W2  = (const float*)d_in[11];
    const float* b2  = (const float*)d_in[12];
    const float* W3  = (const float*)d_in[13];
    const float* b3  = (const float*)d_in[14];
    float* out = (float*)d_out;

    precompute_kernel<<<N_TOK / 4, 256>>>(x, Wf, bf, Wp1, bp1, Wp2, bp2,
                                          Wn, bn, W1, b1);
    dim3 grid(NSEQ / TJ, NSEQ / TI, BATCH);
    dim3 blk(TJ, TI);
    pair_kernel<<<grid, blk>>>(W2, b2, W3, b3, out);
}

// round 3
// speedup vs baseline: 1.5427x; 1.5427x over previous
#include <cuda_runtime.h>

#define BATCH 4
#define NSEQ  512
#define N_TOK (BATCH * NSEQ)   // 2048
#define D     64

// Scratch for per-token vectors (allocation-free rule: __device__ globals)
__device__ float g_a[N_TOK * D];   // a = emb @ W1[:64] + b1   (b1 folded)
__device__ float g_b[N_TOK * D];   // b = emb @ W1[64:]

// ---------------------------------------------------------------------------
// Phase 1: per-token chain  x -> pos -> proj -> emb -> (a, b)
// ---------------------------------------------------------------------------
__global__ void precompute_kernel(
    const float* __restrict__ x,
    const float* __restrict__ Wf,  const float* __restrict__ bf,
    const float* __restrict__ Wp1, const float* __restrict__ bp1,
    const float* __restrict__ Wp2, const float* __restrict__ bp2,
    const float* __restrict__ Wn,  const float* __restrict__ bn,
    const float* __restrict__ W1,  const float* __restrict__ b1)
{
    __shared__ float s_x [4][16];
    __shared__ float s_h [4][D];
    __shared__ float s_h2[4][D];

    const int tl = threadIdx.x >> 6;   // token slot 0..3
    const int d  = threadIdx.x & 63;   // channel
    const int t  = blockIdx.x * 4 + tl;

    if (d < 16) s_x[tl][d] = x[t * 16 + d];
    __syncthreads();

    float ph = bp1[d];
    #pragma unroll
    for (int r = 0; r < 3; r++) ph += s_x[tl][13 + r] * Wp1[r * D + d];
    s_h[tl][d] = fmaxf(ph, 0.f);
    __syncthreads();

    float pos = bp2[d];
    #pragma unroll
    for (int k = 0; k < D; k++) pos += s_h[tl][k] * Wp2[k * D + d];
    float proj = bf[d] + pos;
    #pragma unroll
    for (int r = 0; r < 13; r++) proj += s_x[tl][r] * Wf[r * D + d];
    s_h2[tl][d] = proj;
    __syncthreads();

    float emb = bn[d];
    #pragma unroll
    for (int k = 0; k < D; k++) emb += s_h2[tl][k] * Wn[k * D + d];
    s_h[tl][d] = emb;
    __syncthreads();

    float av = b1[d];
    float bv = 0.f;
    #pragma unroll
    for (int k = 0; k < D; k++) {
        float e = s_h[tl][k];
        av += e * W1[k * D + d];
        bv += e * W1[(D + k) * D + d];
    }
    g_a[t * D + d] = av;
    g_b[t * D + d] = bv;
}

// ---------------------------------------------------------------------------
// Phase 2: pairwise kernel.
//   Block = 256 threads = (32 j-lanes) x (8 i-threads); each thread computes
//   2 pairs: (i0+ty, j0+tx) and (i0+ty+8, j0+tx).  Tile = 16 x 32 pairs.
//   W2 read from shared as ulonglong2 (LDS.128, two packed f32x2 lanes),
//   amortized over 2 pairs -> 32 FFMA2 per 8 weight loads per k.
// ---------------------------------------------------------------------------
#define TI 16
#define TJ 32
#define BSTRIDE 33   // padded stride for b_sT (conflict-free)

__global__ void __launch_bounds__(256)
pair_kernel(const float* __restrict__ W2, const float* __restrict__ b2,
            const float* __restrict__ W3, const float* __restrict__ b3,
            float* __restrict__ out)
{
    __shared__ float a_s [TI * D];                         // [i][k]
    __shared__ float b_sT[D * BSTRIDE];                    // [k][j] padded
    __shared__ __align__(16) float w2_s[D * 32];           // [k][n]
    __shared__ float b2_s[32];
    __shared__ float w3_s[32];

    const int tid = threadIdx.x;
    const int tx  = tid & 31;          // j lane
    const int ty  = tid >> 5;          // 0..7
    const int batch = blockIdx.z;
    const int i0 = blockIdx.y * TI;
    const int j0 = blockIdx.x * TJ;
    const int base = batch * NSEQ;

    // ---- cooperative staging ----
    #pragma unroll
    for (int idx = tid; idx < TI * D; idx += 256)
        a_s[idx] = g_a[(base + i0) * D + idx];

    #pragma unroll
    for (int idx = tid; idx < TJ * D; idx += 256) {
        int jj = idx >> 6, k = idx & 63;                   // coalesced gmem read
        b_sT[k * BSTRIDE + jj] = g_b[(base + j0 + jj) * D + k];
    }

    {   // W2: 2048 floats as 512 float4
        const float4* W2v = (const float4*)W2;
        float4* w2v = (float4*)w2_s;
        #pragma unroll
        for (int idx = tid; idx < 512; idx += 256) w2v[idx] = W2v[idx];
    }
    if (tid < 32) { b2_s[tid] = b2[tid]; w3_s[tid] = W3[tid]; }
    __syncthreads();

    // ---- mainloop: 2 pairs/thread, 32 packed accumulators each ----
    unsigned long long acc0[16], acc1[16];
    #pragma unroll
    for (int n = 0; n < 16; n++) { acc0[n] = 0ull; acc1[n] = 0ull; }

    const float* arow0 = &a_s[ty * D];
    const float* arow1 = &a_s[(ty + 8) * D];
    const float* bcol  = &b_sT[tx];
    const ulonglong2* w2p = (const ulonglong2*)w2_s;       // [k][8]

    #pragma unroll 8
    for (int k = 0; k < D; k++) {
        float bv = bcol[k * BSTRIDE];
        float h0 = fmaxf(arow0[k] + bv, 0.f);
        float h1 = fmaxf(arow1[k] + bv, 0.f);
        unsigned long long H0, H1;
        asm("mov.b64 %0, {%1, %1};" : "=l"(H0) : "r"(__float_as_uint(h0)));
        asm("mov.b64 %0, {%1, %1};" : "=l"(H1) : "r"(__float_as_uint(h1)));
        #pragma unroll
        for (int q = 0; q < 8; q++) {
            ulonglong2 w = w2p[k * 8 + q];                 // LDS.128 broadcast
            asm("fma.rn.f32x2 %0, %1, %2, %0;" : "+l"(acc0[2*q  ]) : "l"(H0), "l"(w.x));
            asm("fma.rn.f32x2 %0, %1, %2, %0;" : "+l"(acc0[2*q+1]) : "l"(H0), "l"(w.y));
            asm("fma.rn.f32x2 %0, %1, %2, %0;" : "+l"(acc1[2*q  ]) : "l"(H1), "l"(w.x));
            asm("fma.rn.f32x2 %0, %1, %2, %0;" : "+l"(acc1[2*q+1]) : "l"(H1), "l"(w.y));
        }
    }

    // ---- epilogue: h2 = relu(acc + b2); logit = h2 @ W3 + b3 ----
    float logit0 = b3[0];
    float logit1 = b3[0];
    #pragma unroll
    for (int n = 0; n < 16; n++) {
        unsigned int lo, hi;
        float c0 = b2_s[2 * n], c1 = b2_s[2 * n + 1];
        float w0 = w3_s[2 * n], w1 = w3_s[2 * n + 1];
        asm("mov.b64 {%0, %1}, %2;" : "=r"(lo), "=r"(hi) : "l"(acc0[n]));
        logit0 += fmaxf(__uint_as_float(lo) + c0, 0.f) * w0
                + fmaxf(__uint_as_float(hi) + c1, 0.f) * w1;
        asm("mov.b64 {%0, %1}, %2;" : "=r"(lo), "=r"(hi) : "l"(acc1[n]));
        logit1 += fmaxf(__uint_as_float(lo) + c0, 0.f) * w0
                + fmaxf(__uint_as_float(hi) + c1, 0.f) * w1;
    }
    float* obase = out + (size_t)batch * NSEQ * NSEQ + j0 + tx;
    obase[(size_t)(i0 + ty)     * NSEQ] = logit0;
    obase[(size_t)(i0 + ty + 8) * NSEQ] = logit1;
}

// ---------------------------------------------------------------------------
extern "C" void kernel_launch(void* const* d_in, const int* in_sizes, int n_in,
                              void* d_out, int out_size)
{
    const float* x   = (const float*)d_in[0];
    const float* Wf  = (const float*)d_in[1];
    const float* bf  = (const float*)d_in[2];
    const float* Wp1 = (const float*)d_in[3];
    const float* bp1 = (const float*)d_in[4];
    const float* Wp2 = (const float*)d_in[5];
    const float* bp2 = (const float*)d_in[6];
    const float* Wn  = (const float*)d_in[7];
    const float* bn  = (const float*)d_in[8];
    const float* W1  = (const float*)d_in[9];
    const float* b1  = (const float*)d_in[10];
    const float* W2  = (const float*)d_in[11];
    const float* b2  = (const float*)d_in[12];
    const float* W3  = (const float*)d_in[13];
    const float* b3  = (const float*)d_in[14];
    float* out = (float*)d_out;

    precompute_kernel<<<N_TOK / 4, 256>>>(x, Wf, bf, Wp1, bp1, Wp2, bp2,
                                          Wn, bn, W1, b1);
    dim3 grid(NSEQ / TJ, NSEQ / TI, BATCH);
    pair_kernel<<<grid, 256>>>(W2, b2, W3, b3, out);
}